// round 17
// baseline (speedup 1.0000x reference)
#include <cuda_runtime.h>
#include <cuda_fp16.h>
#include <math.h>
#include <stdint.h>

#define D    1024
#define E    8
#define HID  4096
#define NMAX 2048

// ---------------- device scratch (static globals: allowed) ----------------
__device__ __half g_Xh[NMAX * D];
__device__ __half g_W1h[E * D * HID];
__device__ __half g_W2h[E * HID * D];
__device__ __half g_Hh[2 * NMAX * HID];
__device__ int   g_cnt[E];      // zeroed statically + by finalize (proven)
__device__ int   g_list[E * NMAX];   // packed-slot -> token
__device__ float g_wrow[E * NMAX];   // packed-slot -> combine weight
__device__ float g_imp[E];
__device__ float g_lse2;

// ---------------- helpers ----------------
__device__ __forceinline__ uint32_t smem_u32(const void* p) {
    uint32_t a;
    asm("{ .reg .u64 t; cvta.to.shared.u64 t, %1; cvt.u32.u64 %0, t; }"
        : "=r"(a) : "l"(p));
    return a;
}

__device__ __forceinline__ void cpasync16(uint32_t dst, const void* src, uint32_t bytes) {
    asm volatile("cp.async.cg.shared.global [%0], [%1], 16, %2;"
                 :: "r"(dst), "l"(src), "r"(bytes));
}
#define CP_COMMIT() asm volatile("cp.async.commit_group;")
#define CP_WAITG0() asm volatile("cp.async.wait_group 0;")

__device__ __forceinline__ void ldsm4(uint32_t* r, uint32_t addr) {
    asm volatile("ldmatrix.sync.aligned.m8n8.x4.shared.b16 {%0,%1,%2,%3}, [%4];"
                 : "=r"(r[0]), "=r"(r[1]), "=r"(r[2]), "=r"(r[3]) : "r"(addr));
}
__device__ __forceinline__ void ldsm4t(uint32_t* r, uint32_t addr) {
    asm volatile("ldmatrix.sync.aligned.m8n8.x4.trans.shared.b16 {%0,%1,%2,%3}, [%4];"
                 : "=r"(r[0]), "=r"(r[1]), "=r"(r[2]), "=r"(r[3]) : "r"(addr));
}
__device__ __forceinline__ void mma_f16(float* c, const uint32_t* a, const uint32_t* b) {
    asm volatile(
        "mma.sync.aligned.m16n8k16.row.col.f32.f16.f16.f32 "
        "{%0,%1,%2,%3}, {%4,%5,%6,%7}, {%8,%9}, {%0,%1,%2,%3};"
        : "+f"(c[0]), "+f"(c[1]), "+f"(c[2]), "+f"(c[3])
        : "r"(a[0]), "r"(a[1]), "r"(a[2]), "r"(a[3]), "r"(b[0]), "r"(b[1]));
}

__device__ __forceinline__ float gelu_tanh(float v) {
    const float c = 0.7978845608028654f;
    float t = tanhf(c * (v + 0.044715f * v * v * v));
    return 0.5f * v * (1.0f + t);
}

// ---------------- conversion kernels ----------------
#define C4W (E * D * HID / 4)
#define C4X (NMAX * D / 4)

// convert a [lo, hi) range of W1 float4s to fp16 (halves run on both streams)
__global__ void split_w1_part(const float* __restrict__ W1, long long lo, long long hi) {
    long long i = lo + (long long)blockIdx.x * blockDim.x + threadIdx.x;
    if (i >= hi) return;
    float4 v = ((const float4*)W1)[i];
    __half2 a = __floats2half2_rn(v.x, v.y);
    __half2 b = __floats2half2_rn(v.z, v.w);
    ((uint2*)g_W1h)[i] = make_uint2(*reinterpret_cast<uint32_t*>(&a),
                                    *reinterpret_cast<uint32_t*>(&b));
}

// W2 -> fp16; side stream, overlapped with ffn1
__global__ void split_w2(const float* __restrict__ W2) {
    long long i = (long long)blockIdx.x * blockDim.x + threadIdx.x;
    if (i >= C4W) return;
    float4 v = ((const float4*)W2)[i];
    __half2 a = __floats2half2_rn(v.x, v.y);
    __half2 b = __floats2half2_rn(v.z, v.w);
    ((uint2*)g_W2h)[i] = make_uint2(*reinterpret_cast<uint32_t*>(&a),
                                    *reinterpret_cast<uint32_t*>(&b));
}

// ---------------- router: zero out, convert x, route ----------------
__global__ void router_kernel(const float* __restrict__ x,
                              const float* __restrict__ Wr,
                              const float* __restrict__ br, int N,
                              float* __restrict__ out) {
    long long nt = (long long)gridDim.x * blockDim.x;
    long long tid0 = (long long)blockIdx.x * blockDim.x + threadIdx.x;
    // zero out[0 .. N*D)
    for (long long i = tid0; i < (long long)N * D / 4; i += nt)
        ((float4*)out)[i] = make_float4(0.f, 0.f, 0.f, 0.f);
    // convert x -> g_Xh
    for (long long i = tid0; i < C4X; i += nt) {
        float4 v = ((const float4*)x)[i];
        __half2 a = __floats2half2_rn(v.x, v.y);
        __half2 b = __floats2half2_rn(v.z, v.w);
        ((uint2*)g_Xh)[i] = make_uint2(*reinterpret_cast<uint32_t*>(&a),
                                       *reinterpret_cast<uint32_t*>(&b));
    }

    int gwarp = (int)(tid0 >> 5);
    int lane  = threadIdx.x & 31;
    if (gwarp >= N) return;
    int t = gwarp;
    const float* xr = x + (size_t)t * D;

    float acc[E];
#pragma unroll
    for (int e = 0; e < E; e++) acc[e] = 0.0f;
    for (int d = lane; d < D; d += 32) {
        float xv = xr[d];
        const float4* w4 = (const float4*)(Wr + (size_t)d * E);
        float4 wa = w4[0], wb = w4[1];
        acc[0] += xv * wa.x; acc[1] += xv * wa.y;
        acc[2] += xv * wa.z; acc[3] += xv * wa.w;
        acc[4] += xv * wb.x; acc[5] += xv * wb.y;
        acc[6] += xv * wb.z; acc[7] += xv * wb.w;
    }
#pragma unroll
    for (int e = 0; e < E; e++) {
#pragma unroll
        for (int off = 16; off; off >>= 1)
            acc[e] += __shfl_down_sync(0xffffffffu, acc[e], off);
    }

    if (lane == 0) {
        float l[E];
#pragma unroll
        for (int e = 0; e < E; e++) l[e] = acc[e] + br[e];
        float m = l[0];
#pragma unroll
        for (int e = 1; e < E; e++) m = fmaxf(m, l[e]);
        float p[E]; float s = 0.0f;
#pragma unroll
        for (int e = 0; e < E; e++) { p[e] = expf(l[e] - m); s += p[e]; }
        float inv = 1.0f / s;
        float lse = m + logf(s);
        atomicAdd(&g_lse2, lse * lse);

        int i0 = 0, i1 = 0; float p0 = -1.0f, p1 = -1.0f;
#pragma unroll
        for (int e = 0; e < E; e++) {
            float pe = p[e] * inv;
            atomicAdd(&g_imp[e], pe);
            if (pe > p0)      { p1 = p0; i1 = i0; p0 = pe; i0 = e; }
            else if (pe > p1) { p1 = pe; i1 = e; }
        }
        float wsum = p0 + p1 + 1e-12f;
        float w0 = p0 / wsum, w1 = p1 / wsum;
        int pos0 = atomicAdd(&g_cnt[i0], 1);
        int pos1 = atomicAdd(&g_cnt[i1], 1);
        g_list[i0 * NMAX + pos0] = t;  g_wrow[i0 * NMAX + pos0] = w0;
        g_list[i1 * NMAX + pos1] = t;  g_wrow[i1 * NMAX + pos1] = w1;
    }
}

// ---------------- mma.sync GEMM: tile 128(M)x64(N), BK=64, warp tile 32x32 ----------------
// 256 threads = 8 warps (4 M x 2 N). 2-stage cp.async ring, one barrier per chunk,
// issue AFTER compute. Stage: A[128][144B] + B[64][144B] = 27648 B; x2 = 55296
// -> 3 CTAs/SM (smem 166KB, regs capped at 85 via launch_bounds(256,3)).
#define A_LD_B   144     // A row pitch bytes (64 f16 + 16B pad)
#define B_LD_B   144     // B row pitch bytes (64 f16 + 16B pad)
#define A_SZ (128 * A_LD_B)   // 18432
#define B_SZ (64 * B_LD_B)    // 9216
#define STAGE_BYTES (A_SZ + B_SZ)           // 27648
#define SMEM_TOTAL  (2 * STAGE_BYTES)       // 55296

template<int PHASE, int SPLITK>
__global__ __launch_bounds__(256, 3) void ffn_mma(
    const __half* __restrict__ Wh,
    const float* __restrict__ bias,
    float* __restrict__ out)
{
    constexpr int KDIM = (PHASE == 1) ? D : HID;
    constexpr int NDIM = (PHASE == 1) ? HID : D;
    constexpr int KSEG = KDIM / SPLITK;
    constexpr int NCH  = KSEG / 64;

    int e   = blockIdx.z / SPLITK;
    int ksp = blockIdx.z % SPLITK;
    int n = g_cnt[e];
    int r0 = blockIdx.y * 128;
    if (r0 >= n) return;
    int c0 = blockIdx.x * 64;
    // inline prefix sum over tiny g_cnt (replaces scan kernel)
    int base = 0;
#pragma unroll
    for (int eo = 0; eo < E; eo++) base += (eo < e) ? g_cnt[eo] : 0;
    size_t kbase = (size_t)ksp * KSEG;

    extern __shared__ char smem[];
    uint32_t sb = smem_u32(smem);
    int t = threadIdx.x;
    int lane = t & 31, wid = t >> 5;

    // ---- A cp.async: row = t>>1 (2 threads/row), 4 x 16B each ----
    int arow = t >> 1;
    const char* asrc;
    uint32_t abytes;
    {
        int rowg = r0 + arow;
        bool valid = rowg < n;
        size_t off;
        if (PHASE == 1) {
            int tok = valid ? g_list[e * NMAX + rowg] : 0;
            off = (size_t)tok * D + kbase + (t & 1) * 32;
            asrc = (const char*)(g_Xh + off);
        } else {
            int rr = valid ? rowg : 0;
            off = (size_t)(base + rr) * HID + kbase + (t & 1) * 32;
            asrc = (const char*)(g_Hh + off);
        }
        abytes = valid ? 16u : 0u;
    }
    uint32_t adst = (uint32_t)(arow * A_LD_B + (t & 1) * 64);

    // ---- B cp.async: k-row = t>>2 (4 threads/row), 2 x 16B each ----
    int bk0 = t >> 2;
    size_t wbase = (size_t)e * KDIM * NDIM + (kbase + bk0) * NDIM + c0 + (t & 3) * 16;
    const char* bsrc = (const char*)(Wh + wbase);
    uint32_t bdst = (uint32_t)(bk0 * B_LD_B + (t & 3) * 32);

    auto issue = [&](int kc, int stage) {
        uint32_t s0 = sb + stage * STAGE_BYTES;
        size_t aoff = (size_t)kc * 128;                // 64 f16 = 128 bytes
        size_t boff = (size_t)kc * 64 * NDIM * 2;      // bytes
#pragma unroll
        for (int q = 0; q < 4; q++)
            cpasync16(s0 + adst + q * 16, asrc + aoff + q * 16, abytes);
        uint32_t bb = s0 + A_SZ;
#pragma unroll
        for (int q = 0; q < 2; q++)
            cpasync16(bb + bdst + q * 16, bsrc + boff + q * 16, 16);
    };

    // ---- per-warp ldmatrix lane offsets ----
    int m0  = (wid & 3) * 32;
    int n0w = (wid >> 2) * 32;
    uint32_t a_lane = (uint32_t)((m0 + (lane & 15)) * A_LD_B + (lane >> 4) * 16);
    uint32_t b_lane = (uint32_t)(((lane & 7) + 8 * ((lane >> 3) & 1)) * B_LD_B
                                 + (n0w + 8 * (lane >> 4)) * 2);

    float acc[2][4][4];
#pragma unroll
    for (int mt = 0; mt < 2; mt++)
#pragma unroll
        for (int nt = 0; nt < 4; nt++)
#pragma unroll
            for (int q = 0; q < 4; q++) acc[mt][nt][q] = 0.0f;

    // 2-stage prologue: 1 chunk in flight
    issue(0, 0); CP_COMMIT();

    for (int kc = 0; kc < NCH; kc++) {
        CP_WAITG0();                     // chunk kc landed (this thread)
        __syncthreads();                 // all landed; all warps done reading other stage

        uint32_t sA = sb + (kc & 1) * STAGE_BYTES;
        uint32_t sB = sA + A_SZ;

#pragma unroll
        for (int ks = 0; ks < 4; ks++) {       // k sub-steps of 16 (BK=64)
            uint32_t af[2][4];
#pragma unroll
            for (int mt = 0; mt < 2; mt++)
                ldsm4(af[mt], sA + a_lane + mt * 16 * A_LD_B + ks * 32);
#pragma unroll
            for (int g = 0; g < 2; g++) {      // n groups of 16 cols
                uint32_t bh[4];
                ldsm4t(bh, sB + b_lane + ks * 16 * B_LD_B + g * 32);
#pragma unroll
                for (int mt = 0; mt < 2; mt++) {
#pragma unroll
                    for (int sub = 0; sub < 2; sub++) {
                        mma_f16(acc[mt][g * 2 + sub], af[mt], &bh[sub * 2]);
                    }
                }
            }
        }

        if (kc + 1 < NCH) issue(kc + 1, (kc + 1) & 1);   // AFTER compute
        CP_COMMIT();                                     // uniform group count
    }

    // ---- epilogue ----
    int lr = lane >> 2;
    int lc = (lane & 3) * 2;

    if (PHASE == 1) {
#pragma unroll
        for (int mt = 0; mt < 2; mt++) {
#pragma unroll
            for (int nt = 0; nt < 4; nt++) {
                int col = c0 + n0w + nt * 8 + lc;
                float bz0 = bias[e * NDIM + col];
                float bz1 = bias[e * NDIM + col + 1];
                int ra = r0 + m0 + mt * 16 + lr;
                int rb = ra + 8;
                float* a = acc[mt][nt];
                if (ra < n) {
                    float v0 = gelu_tanh(a[0] + bz0);
                    float v1 = gelu_tanh(a[1] + bz1);
                    __half2 h = __floats2half2_rn(v0, v1);
                    *(uint32_t*)(g_Hh + (size_t)(base + ra) * HID + col)
                        = *reinterpret_cast<uint32_t*>(&h);
                }
                if (rb < n) {
                    float v0 = gelu_tanh(a[2] + bz0);
                    float v1 = gelu_tanh(a[3] + bz1);
                    __half2 h = __floats2half2_rn(v0, v1);
                    *(uint32_t*)(g_Hh + (size_t)(base + rb) * HID + col)
                        = *reinterpret_cast<uint32_t*>(&h);
                }
            }
        }
    } else {
        // fused combine: out[token, col] += w * (acc + bias); bias only from split 0
        float bscale = (ksp == 0) ? 1.0f : 0.0f;
#pragma unroll
        for (int mt = 0; mt < 2; mt++) {
            int ra = r0 + m0 + mt * 16 + lr;
            int rb = ra + 8;
            int tokA = 0, tokB = 0; float wA = 0.f, wB = 0.f;
            if (ra < n) { tokA = g_list[e * NMAX + ra]; wA = g_wrow[e * NMAX + ra]; }
            if (rb < n) { tokB = g_list[e * NMAX + rb]; wB = g_wrow[e * NMAX + rb]; }
#pragma unroll
            for (int nt = 0; nt < 4; nt++) {
                int col = c0 + n0w + nt * 8 + lc;
                float bz0 = bscale * bias[e * NDIM + col];
                float bz1 = bscale * bias[e * NDIM + col + 1];
                float* a = acc[mt][nt];
                if (ra < n) {
                    atomicAdd(&out[(size_t)tokA * D + col],     wA * (a[0] + bz0));
                    atomicAdd(&out[(size_t)tokA * D + col + 1], wA * (a[1] + bz1));
                }
                if (rb < n) {
                    atomicAdd(&out[(size_t)tokB * D + col],     wB * (a[2] + bz0));
                    atomicAdd(&out[(size_t)tokB * D + col + 1], wB * (a[3] + bz1));
                }
            }
        }
    }
}

// ---------------- finalize (self-cleans counters for next replay) ----------------
__global__ void finalize_kernel(float* __restrict__ out, int N, long long out_size) {
    if (threadIdx.x == 0) {
        float invN = 1.0f / (float)N;
        float z = g_lse2 * invN;
        float s = 0.0f;
        for (int e = 0; e < E; e++)
            s += (g_imp[e] * invN) * ((float)g_cnt[e] * invN);
        long long base = (long long)N * D;
        out[base]     = z;
        out[base + 1] = (float)E * s;
        for (long long i = base + 2; i < out_size; i++) out[i] = 0.0f;
        // self-clean: next replay starts from zeroed counters
        g_lse2 = 0.0f;
        for (int e = 0; e < E; e++) { g_cnt[e] = 0; g_imp[e] = 0.0f; }
    }
}

extern "C" void kernel_launch(void* const* d_in, const int* in_sizes, int n_in,
                              void* d_out, int out_size) {
    const float* x  = (const float*)d_in[0];
    const float* Wr = (const float*)d_in[1];
    const float* br = (const float*)d_in[2];
    const float* W1 = (const float*)d_in[3];
    const float* b1 = (const float*)d_in[4];
    const float* W2 = (const float*)d_in[5];
    const float* b2 = (const float*)d_in[6];
    float* out = (float*)d_out;

    int N = in_sizes[0] / D;  // 2048

    void *p_w1h, *p_w2h;
    cudaGetSymbolAddress(&p_w1h, g_W1h);
    cudaGetSymbolAddress(&p_w2h, g_W2h);

    cudaFuncSetAttribute(ffn_mma<1, 1>, cudaFuncAttributeMaxDynamicSharedMemorySize, SMEM_TOTAL);
    cudaFuncSetAttribute(ffn_mma<2, 2>, cudaFuncAttributeMaxDynamicSharedMemorySize, SMEM_TOTAL);

    // side stream + events (created per call; not destroyed — capture-safe)
    cudaStream_t s2;
    cudaEvent_t evFork, evReady, evW2;
    cudaStreamCreateWithFlags(&s2, cudaStreamNonBlocking);
    cudaEventCreateWithFlags(&evFork,  cudaEventDisableTiming);
    cudaEventCreateWithFlags(&evReady, cudaEventDisableTiming);
    cudaEventCreateWithFlags(&evW2,    cudaEventDisableTiming);

    cudaEventRecord(evFork, 0);
    cudaStreamWaitEvent(s2, evFork, 0);

    long long halfW = C4W / 2;
    // launch #1 (main): W1 first half
    split_w1_part<<<(int)((halfW + 255) / 256), 256>>>(W1, 0, halfW);
    // launch #2 (s2): W1 second half
    split_w1_part<<<(int)((halfW + 255) / 256), 256, 0, s2>>>(W1, halfW, C4W);
    // launch #3 (s2): router (zero out + convert x + route)
    {
        int warps_per_block = 8;
        int blocks = (N + warps_per_block - 1) / warps_per_block;
        router_kernel<<<blocks, warps_per_block * 32, 0, s2>>>(x, Wr, br, N, out);
    }
    cudaEventRecord(evReady, s2);

    // launch #4 (main): ffn1  <-- ncu capture slot
    cudaStreamWaitEvent(0, evReady, 0);
    {
        dim3 grid(HID / 64, NMAX / 128, E);        // 64 x 16 x 8 = 8192
        ffn_mma<1, 1><<<grid, 256, SMEM_TOTAL>>>((const __half*)p_w1h, b1, out);
    }
    // launch #5 (s2): W2 convert — overlaps ffn1
    split_w2<<<(C4W + 255) / 256, 256, 0, s2>>>(W2);
    cudaEventRecord(evW2, s2);

    // launch #6 (main): ffn2 (split-K=2, fused combine)
    cudaStreamWaitEvent(0, evW2, 0);
    {
        dim3 grid(D / 64, NMAX / 128, E * 2);      // 16 x 16 x 16 = 4096
        ffn_mma<2, 2><<<grid, 256, SMEM_TOTAL>>>((const __half*)p_w2h, b2, out);
    }
    // launch #7 (main): finalize + self-clean
    finalize_kernel<<<1, 32>>>(out, N, (long long)out_size);
}